// round 10
// baseline (speedup 1.0000x reference)
#include <cuda_runtime.h>
#include <math.h>

// input:  (B=2, T=2048, V=32000) f32 ; target: (2, 2048) int32 ; out: scalar f32
// ct_len = 512, win = 256
#define B_DIM 2
#define T_DIM 2048
#define V_DIM 32000
#define CT_LEN 512
#define WIN 256
#define ROWS (B_DIM * CT_LEN)      // 1024
#define IGNORE_INDEX (-100)
#define PAD_ID 0

#define WARPS_PER_CTA 8
#define CTA_THREADS (WARPS_PER_CTA * 32)      // 256
#define GRID_CTAS (ROWS / WARPS_PER_CTA)      // 128
#define NEGS_PER_LANE (WIN / 32)              // 8

// Allocation-free accumulators. Last CTA resets them each call; graph replays
// are stream-serialized, so every replay starts from zero.
__device__ float        g_loss_sum  = 0.0f;
__device__ float        g_valid_sum = 0.0f;
__device__ unsigned int g_done      = 0u;

__device__ __forceinline__ void cp_async_4(unsigned smem_addr, const void* gptr) {
    asm volatile("cp.async.ca.shared.global [%0], [%1], 4;"
                 :: "r"(smem_addr), "l"(gptr) : "memory");
}

__global__ __launch_bounds__(CTA_THREADS, 8)
void ctl_cpasync_kernel(const float* __restrict__ input,
                        const int* __restrict__ target,
                        float* __restrict__ out)
{
    // Staging: thread-private 8-float runs, [tid][k] layout.
    __shared__ float s_gather[CTA_THREADS * NEGS_PER_LANE];   // 8 KB

    const int tid  = threadIdx.x;
    const int lane = tid & 31;
    const int w    = tid >> 5;
    const int row  = blockIdx.x * WARPS_PER_CTA + w;  // 0..1023
    const int b    = row >> 9;                        // / CT_LEN
    const int i    = row & (CT_LEN - 1);

    const int tbase = b * T_DIM;
    const long long lbase = ((long long)(b * T_DIM + i)) * V_DIM;

    // --- batch 1: coalesced target loads + row target (broadcast) ---
    const int t = __ldg(&target[tbase + i]);
    int tj[NEGS_PER_LANE];
    #pragma unroll
    for (int k = 0; k < NEGS_PER_LANE; k++) {
        const int j = i - WIN + k * 32 + lane;
        tj[k] = (j >= 0) ? __ldg(&target[tbase + j]) : PAD_ID;
    }

    const int vrow = (t != IGNORE_INDEX);
    int ts = vrow ? t : PAD_ID;
    ts = ts < 0 ? 0 : (ts >= V_DIM ? V_DIM - 1 : ts);

    // --- batch 2: 8 async gathers into smem (deep outstanding queue) ---
    const unsigned s_base = (unsigned)__cvta_generic_to_shared(
                                &s_gather[tid * NEGS_PER_LANE]);
    #pragma unroll
    for (int k = 0; k < NEGS_PER_LANE; k++) {
        int c = tj[k];
        int idx = c < 0 ? 0 : (c >= V_DIM ? V_DIM - 1 : c);  // PAD/j<0 -> idx 0
        cp_async_4(s_base + 4u * k, &input[lbase + idx]);
    }
    asm volatile("cp.async.commit_group;" ::: "memory");

    // pos: one address per warp, broadcast LDG — overlaps with async fills
    const float pos = __ldg(&input[lbase + ts]);

    asm volatile("cp.async.wait_group 0;" ::: "memory");

    // --- compute + warp reduction (each thread reads only its own slots) ---
    float e = 0.0f;
    #pragma unroll
    for (int k = 0; k < NEGS_PER_LANE; k++) {
        if (tj[k] != PAD_ID)                      // j<0 lanes have tj==PAD -> excluded
            e += __expf(s_gather[tid * NEGS_PER_LANE + k] - pos);
    }
    #pragma unroll
    for (int o = 16; o > 0; o >>= 1)
        e += __shfl_down_sync(0xffffffffu, e, o);

    if (lane == 0) {
        if (vrow) {
            atomicAdd(&g_loss_sum, log1pf(e));
            atomicAdd(&g_valid_sum, 1.0f);
        }
    }

    // --- ticket: last CTA finalizes ---
    __shared__ int s_last;
    __syncthreads();
    if (tid == 0) {
        __threadfence();
        unsigned int ticket = atomicAdd(&g_done, 1u);
        s_last = (ticket == (unsigned int)(GRID_CTAS - 1));
    }
    __syncthreads();

    if (s_last && tid == 0) {
        __threadfence();
        float l = g_loss_sum;
        float v = g_valid_sum;
        out[0] = l / fmaxf(v, 1.0f);
        g_loss_sum  = 0.0f;
        g_valid_sum = 0.0f;
        g_done      = 0u;
    }
}

extern "C" void kernel_launch(void* const* d_in, const int* in_sizes, int n_in,
                              void* d_out, int out_size)
{
    const float* input  = (const float*)d_in[0];
    const int*   target = (const int*)d_in[1];
    float*       out    = (float*)d_out;

    (void)in_sizes; (void)n_in; (void)out_size;

    ctl_cpasync_kernel<<<GRID_CTAS, CTA_THREADS>>>(input, target, out);
}

// round 11
// speedup vs baseline: 1.1582x; 1.1582x over previous
#include <cuda_runtime.h>
#include <math.h>

// input:  (B=2, T=2048, V=32000) f32 ; target: (2, 2048) int32 ; out: scalar f32
// ct_len = 512, win = 256
#define B_DIM 2
#define T_DIM 2048
#define V_DIM 32000
#define CT_LEN 512
#define WIN 256
#define ROWS (B_DIM * CT_LEN)      // 1024
#define IGNORE_INDEX (-100)
#define PAD_ID 0

#define WARPS_PER_CTA 8
#define CTA_THREADS (WARPS_PER_CTA * 32)      // 256
#define GRID_CTAS (ROWS / WARPS_PER_CTA)      // 128
#define NEGS_PER_LANE (WIN / 32)              // 8

// Allocation-free scratch (every element rewritten each call; counter self-resets)
__device__ float        g_row_loss[ROWS];
__device__ float        g_row_valid[ROWS];
__device__ unsigned int g_done = 0u;

__device__ __forceinline__ void prefetch_l2(const void* p) {
    asm volatile("prefetch.global.L2 [%0];" :: "l"(p));
}

__global__ __launch_bounds__(CTA_THREADS, 8)
void ctl_prefetch_kernel(const float* __restrict__ input,
                         const int* __restrict__ target,
                         float* __restrict__ out)
{
    const int tid  = threadIdx.x;
    const int lane = tid & 31;
    const int w    = tid >> 5;
    const int row  = blockIdx.x * WARPS_PER_CTA + w;  // 0..1023
    const int b    = row >> 9;                        // / CT_LEN
    const int i    = row & (CT_LEN - 1);

    const int tbase = b * T_DIM;
    const long long lbase = ((long long)(b * T_DIM + i)) * V_DIM;

    // --- batch 1: coalesced target loads + row target (broadcast) ---
    const int t = __ldg(&target[tbase + i]);
    int tj[NEGS_PER_LANE];
    #pragma unroll
    for (int k = 0; k < NEGS_PER_LANE; k++) {
        const int j = i - WIN + k * 32 + lane;
        tj[k] = (j >= 0) ? __ldg(&target[tbase + j]) : PAD_ID;
    }

    const int vrow = (t != IGNORE_INDEX);
    int ts = vrow ? t : PAD_ID;
    ts = ts < 0 ? 0 : (ts >= V_DIM ? V_DIM - 1 : ts);

    int idxs[NEGS_PER_LANE];
    #pragma unroll
    for (int k = 0; k < NEGS_PER_LANE; k++) {
        int c = tj[k];
        idxs[k] = c < 0 ? 0 : (c >= V_DIM ? V_DIM - 1 : c);  // PAD/j<0 -> idx 0
    }

    // --- phase A: fire-and-forget L2 prefetches. No dst register, no MSHR
    // writeback -> retire immediately; the DRAM drain is scheduled over ALL
    // outstanding prefetched sectors chip-wide, not ~64 demand MSHRs per SM.
    prefetch_l2(&input[lbase + ts]);
    #pragma unroll
    for (int k = 0; k < NEGS_PER_LANE; k++)
        prefetch_l2(&input[lbase + idxs[k]]);

    // --- phase B: demand loads; each MSHR is held only until its (already
    // in-flight) sector lands at L2 -> completions stream at DRAM drain rate.
    const float pos = __ldg(&input[lbase + ts]);
    float nv[NEGS_PER_LANE];
    #pragma unroll
    for (int k = 0; k < NEGS_PER_LANE; k++)
        nv[k] = __ldg(&input[lbase + idxs[k]]);

    // --- compute + warp reduction (no barriers in hot path) ---
    float e = 0.0f;
    #pragma unroll
    for (int k = 0; k < NEGS_PER_LANE; k++) {
        if (tj[k] != PAD_ID)                      // j<0 lanes have tj==PAD -> excluded
            e += __expf(nv[k] - pos);
    }
    #pragma unroll
    for (int o = 16; o > 0; o >>= 1)
        e += __shfl_down_sync(0xffffffffu, e, o);

    if (lane == 0) {
        g_row_loss[row]  = vrow ? log1pf(e) : 0.0f;
        g_row_valid[row] = (float)vrow;
    }

    // --- last-CTA final reduction ---
    __shared__ int s_last;
    __syncthreads();
    if (tid == 0) {
        __threadfence();
        unsigned int ticket = atomicAdd(&g_done, 1u);
        s_last = (ticket == (unsigned int)(GRID_CTAS - 1));
    }
    __syncthreads();

    if (s_last) {
        float l = 0.0f, v = 0.0f;
        #pragma unroll
        for (int k = 0; k < ROWS / CTA_THREADS; k++) {
            l += g_row_loss[tid + k * CTA_THREADS];
            v += g_row_valid[tid + k * CTA_THREADS];
        }
        #pragma unroll
        for (int o = 16; o > 0; o >>= 1) {
            l += __shfl_down_sync(0xffffffffu, l, o);
            v += __shfl_down_sync(0xffffffffu, v, o);
        }
        __shared__ float sl[WARPS_PER_CTA];
        __shared__ float sv[WARPS_PER_CTA];
        if (lane == 0) { sl[w] = l; sv[w] = v; }
        __syncthreads();
        if (tid == 0) {
            float l2 = 0.0f, v2 = 0.0f;
            #pragma unroll
            for (int q = 0; q < WARPS_PER_CTA; q++) { l2 += sl[q]; v2 += sv[q]; }
            out[0] = l2 / fmaxf(v2, 1.0f);
            g_done = 0u;                       // reset for next graph replay
        }
    }
}

extern "C" void kernel_launch(void* const* d_in, const int* in_sizes, int n_in,
                              void* d_out, int out_size)
{
    const float* input  = (const float*)d_in[0];
    const int*   target = (const int*)d_in[1];
    float*       out    = (float*)d_out;

    (void)in_sizes; (void)n_in; (void)out_size;

    ctl_prefetch_kernel<<<GRID_CTAS, CTA_THREADS>>>(input, target, out);
}